// round 1
// baseline (speedup 1.0000x reference)
#include <cuda_runtime.h>
#include <cuda_bf16.h>
#include <math.h>

// Problem constants
#define B_   8
#define T_   8192
#define C_   128
#define H_   8
#define T0_  16
#define NP_  512           // T/T0
#define S_   65            // T0/4*T0+1 ... actually 4 patches *16 +1 sink
#define EPS_ 1.1920929e-07f

// Scratch (device globals; no allocation allowed)
__device__ float g_logits[B_ * NP_];             // 4096
__device__ int   g_topk[B_ * 4];                 // sorted patch indices per batch
__device__ float g_qkvg[B_ * 64 * 4096];         // 8 MB: qkvg for 64 selected tokens/batch
__device__ float g_y[B_ * 64 * 1024];            // 2 MB: gated attention output (b, s, h*128+c)
__device__ float g_part[4 * B_ * 64 * 128];      // 1 MB: split-K partials of final GEMM

// ---------------------------------------------------------------------------
// Kernel 1: patch score logits.  logit[b,p] = dot(v, pw) * rsqrt(mean(v^2)+eps)
// v = x[b, p*16:(p+1)*16, :] flattened (2048 contiguous floats)
// ---------------------------------------------------------------------------
__global__ void patch_score_kernel(const float* __restrict__ x,
                                   const float* __restrict__ pw) {
    int blk = blockIdx.x;                  // b*512 + p
    const float4* v = reinterpret_cast<const float4*>(x + (size_t)blk * 2048);
    const float4* w = reinterpret_cast<const float4*>(pw);
    float ssq = 0.f, dot = 0.f;
    for (int i = threadIdx.x; i < 512; i += 256) {
        float4 a = v[i];
        float4 b = w[i];
        ssq += a.x * a.x + a.y * a.y + a.z * a.z + a.w * a.w;
        dot += a.x * b.x + a.y * b.y + a.z * b.z + a.w * b.w;
    }
    // warp reduce
    for (int off = 16; off; off >>= 1) {
        ssq += __shfl_xor_sync(0xffffffffu, ssq, off);
        dot += __shfl_xor_sync(0xffffffffu, dot, off);
    }
    __shared__ float red[16];
    int wid = threadIdx.x >> 5, lane = threadIdx.x & 31;
    if (lane == 0) { red[wid] = ssq; red[8 + wid] = dot; }
    __syncthreads();
    if (threadIdx.x == 0) {
        float S = 0.f, D = 0.f;
        for (int wv = 0; wv < 8; wv++) { S += red[wv]; D += red[8 + wv]; }
        g_logits[blk] = D * rsqrtf(S * (1.0f / 2048.0f) + EPS_);
    }
}

// ---------------------------------------------------------------------------
// Kernel 2: top-4 per batch (softmax is monotone -> work on logits), sorted asc
// One warp per batch.
// ---------------------------------------------------------------------------
__global__ void topk_kernel() {
    int b = blockIdx.x;
    int lane = threadIdx.x;   // 32 threads
    float vals[16];
    for (int i = 0; i < 16; i++) vals[i] = g_logits[b * NP_ + lane * 16 + i];
    int chosen[4];
    for (int r = 0; r < 4; r++) {
        float best = -3.4e38f;
        int bi = 0x7fffffff;
        for (int i = 0; i < 16; i++) {
            int idx = lane * 16 + i;
            bool used = false;
            for (int j = 0; j < r; j++) if (chosen[j] == idx) used = true;
            if (!used && vals[i] > best) { best = vals[i]; bi = idx; }
        }
        for (int off = 16; off; off >>= 1) {
            float ov = __shfl_down_sync(0xffffffffu, best, off);
            int   oi = __shfl_down_sync(0xffffffffu, bi, off);
            if (ov > best || (ov == best && oi < bi)) { best = ov; bi = oi; }
        }
        bi = __shfl_sync(0xffffffffu, bi, 0);
        chosen[r] = bi;
    }
    if (lane == 0) {
        // sort 4 ascending
        for (int i = 0; i < 3; i++)
            for (int j = i + 1; j < 4; j++)
                if (chosen[j] < chosen[i]) { int t = chosen[i]; chosen[i] = chosen[j]; chosen[j] = t; }
        for (int i = 0; i < 4; i++) g_topk[b * 4 + i] = chosen[i];
    }
}

// ---------------------------------------------------------------------------
// Kernel 3: qkvg projection for the 64 selected tokens of each batch.
// grid (32 n-tiles, 8 batches); block computes [64 tokens x 128 outputs], K=128
// dynamic smem: xs[64*128] + ws[128*128] (ws stored [k][n]) = 96 KB
// ---------------------------------------------------------------------------
__global__ void qkvg_kernel(const float* __restrict__ x,
                            const float* __restrict__ W) {
    extern __shared__ float sm3[];
    float* xs = sm3;            // 64*128
    float* ws = sm3 + 64 * 128; // 128*128, layout [k][n]
    int b  = blockIdx.y;
    int n0 = blockIdx.x * 128;
    int tid = threadIdx.x;      // 256

    // gather x for 64 tokens (patch-contiguous -> coalesced)
    for (int i = tid; i < 2048; i += 256) {        // 2048 float4
        int m  = i >> 5;
        int c4 = i & 31;
        int tok = g_topk[b * 4 + (m >> 4)] * T0_ + (m & 15);
        reinterpret_cast<float4*>(xs)[i] =
            reinterpret_cast<const float4*>(x + ((size_t)b * T_ + tok) * C_)[c4];
    }
    // load W rows n0..n0+127 transposed into ws[k][n]
    for (int i = tid; i < 4096; i += 256) {        // 4096 float4
        int n  = i >> 5;
        int k4 = i & 31;
        float4 wv = reinterpret_cast<const float4*>(W + (size_t)(n0 + n) * C_)[k4];
        int k = k4 * 4;
        ws[(k + 0) * 128 + n] = wv.x;
        ws[(k + 1) * 128 + n] = wv.y;
        ws[(k + 2) * 128 + n] = wv.z;
        ws[(k + 3) * 128 + n] = wv.w;
    }
    __syncthreads();

    int ty = tid >> 5;   // 0..7  -> rows ty*8 .. ty*8+7
    int tx = tid & 31;   // 0..31 -> cols tx*4 .. tx*4+3
    float acc[8][4];
#pragma unroll
    for (int mm = 0; mm < 8; mm++)
#pragma unroll
        for (int nn = 0; nn < 4; nn++) acc[mm][nn] = 0.f;

    for (int k = 0; k < 128; k++) {
        float4 bv = reinterpret_cast<const float4*>(ws + k * 128)[tx];
#pragma unroll
        for (int mm = 0; mm < 8; mm++) {
            float a = xs[(ty * 8 + mm) * 128 + k];
            acc[mm][0] += a * bv.x;
            acc[mm][1] += a * bv.y;
            acc[mm][2] += a * bv.z;
            acc[mm][3] += a * bv.w;
        }
    }
#pragma unroll
    for (int mm = 0; mm < 8; mm++) {
        int m = ty * 8 + mm;
        float4 o = make_float4(acc[mm][0], acc[mm][1], acc[mm][2], acc[mm][3]);
        reinterpret_cast<float4*>(g_qkvg + ((size_t)(b * 64 + m)) * 4096 + n0)[tx] = o;
    }
}

// ---------------------------------------------------------------------------
// Kernel 4: attention per (b,h).  64 blocks x 256 threads.
// Builds S=65 q/k/v rows (sink + gathered), rope+rmsnorm q/k, causal softmax,
// y = att@v, gate by sigmoid(g), write g_y.
// dynamic smem: q,k,v [65*129] + att [65*66]  (~118 KB)
// ---------------------------------------------------------------------------
__global__ void attn_kernel(const float* __restrict__ cosp,
                            const float* __restrict__ sinp,
                            const float* __restrict__ sink,
                            const float* __restrict__ tao) {
    extern __shared__ float sm4[];
    float* qs  = sm4;
    float* ks_ = sm4 + 65 * 129;
    float* vs  = sm4 + 2 * 65 * 129;
    float* att = sm4 + 3 * 65 * 129;   // stride 66

    int b = blockIdx.x >> 3;
    int h = blockIdx.x & 7;
    int tid  = threadIdx.x;
    int warp = tid >> 5;
    int lane = tid & 31;
    float tao0 = tao[0], tao1 = tao[1];

    // load + rope + rmsnorm q and k; raw copy v
    for (int s = warp; s < S_; s += 8) {
        const float* qsrc;
        const float* ksrc;
        const float* vsrc;
        if (s == 0) {
            qsrc = sink + h * C_;
            ksrc = qsrc;
            vsrc = qsrc;
        } else {
            int sp = s - 1;
            int j = sp >> 4, r = sp & 15;
            size_t base = (size_t)(b * 64 + j * 16) * 4096 + (size_t)(r & 3) * 1024 + h * C_;
            qsrc = g_qkvg + base + (size_t)((r >> 2) + 0) * 4096;
            ksrc = g_qkvg + base + (size_t)((r >> 2) + 4) * 4096;
            vsrc = g_qkvg + base + (size_t)((r >> 2) + 8) * 4096;
        }
        float c0 = cosp[s * 64 + lane],      s0 = sinp[s * 64 + lane];
        float c1 = cosp[s * 64 + lane + 32], s1 = sinp[s * 64 + lane + 32];

        // q
        {
            float a0 = qsrc[lane], a1 = qsrc[lane + 32], a2 = qsrc[lane + 64], a3 = qsrc[lane + 96];
            float o0 =  a0 * c0 + a2 * s0;
            float o2 = -a0 * s0 + a2 * c0;
            float o1 =  a1 * c1 + a3 * s1;
            float o3 = -a1 * s1 + a3 * c1;
            float ss = o0 * o0 + o1 * o1 + o2 * o2 + o3 * o3;
            for (int off = 16; off; off >>= 1) ss += __shfl_xor_sync(0xffffffffu, ss, off);
            float rn = rsqrtf(ss * (1.0f / 128.0f) + EPS_) * tao0;
            qs[s * 129 + lane]      = o0 * rn;
            qs[s * 129 + lane + 32] = o1 * rn;
            qs[s * 129 + lane + 64] = o2 * rn;
            qs[s * 129 + lane + 96] = o3 * rn;
        }
        // k
        {
            float a0 = ksrc[lane], a1 = ksrc[lane + 32], a2 = ksrc[lane + 64], a3 = ksrc[lane + 96];
            float o0 =  a0 * c0 + a2 * s0;
            float o2 = -a0 * s0 + a2 * c0;
            float o1 =  a1 * c1 + a3 * s1;
            float o3 = -a1 * s1 + a3 * c1;
            float ss = o0 * o0 + o1 * o1 + o2 * o2 + o3 * o3;
            for (int off = 16; off; off >>= 1) ss += __shfl_xor_sync(0xffffffffu, ss, off);
            float rn = rsqrtf(ss * (1.0f / 128.0f) + EPS_) * tao1;
            ks_[s * 129 + lane]      = o0 * rn;
            ks_[s * 129 + lane + 32] = o1 * rn;
            ks_[s * 129 + lane + 64] = o2 * rn;
            ks_[s * 129 + lane + 96] = o3 * rn;
        }
        // v raw
        vs[s * 129 + lane]      = vsrc[lane];
        vs[s * 129 + lane + 32] = vsrc[lane + 32];
        vs[s * 129 + lane + 64] = vsrc[lane + 64];
        vs[s * 129 + lane + 96] = vsrc[lane + 96];
    }
    __syncthreads();

    // scores (causal only)
    const float scale = 0.08838834764831845f;  // 1/sqrt(128)
    for (int idx = tid; idx < S_ * S_; idx += 256) {
        int s = idx / S_, t = idx - s * S_;
        if (t > s) continue;
        float acc = 0.f;
#pragma unroll 4
        for (int c = 0; c < 128; c++) acc += qs[s * 129 + c] * ks_[t * 129 + c];
        att[s * 66 + t] = acc * scale;
    }
    __syncthreads();

    // row softmax
    if (tid < S_) {
        int s = tid;
        float m = -3.4e38f;
        for (int t = 0; t <= s; t++) m = fmaxf(m, att[s * 66 + t]);
        float sum = 0.f;
        for (int t = 0; t <= s; t++) {
            float e = expf(att[s * 66 + t] - m);
            att[s * 66 + t] = e;
            sum += e;
        }
        float inv = 1.f / sum;
        for (int t = 0; t <= s; t++) att[s * 66 + t] *= inv;
    }
    __syncthreads();

    // y = att @ v (drop sink row), gate with sigmoid(g), store
    for (int idx = tid; idx < 64 * 128; idx += 256) {
        int sp = idx >> 7;
        int c  = idx & 127;
        int s  = sp + 1;
        float acc = 0.f;
        for (int t = 0; t <= s; t++) acc += att[s * 66 + t] * vs[t * 129 + c];
        int j = sp >> 4, r = sp & 15;
        float gv = g_qkvg[(size_t)(b * 64 + j * 16 + 12 + (r >> 2)) * 4096
                          + (size_t)(r & 3) * 1024 + h * C_ + c];
        float sig = 1.f / (1.f + expf(-gv));
        g_y[(size_t)(b * 64 + sp) * 1024 + h * C_ + c] = acc * sig;
    }
}

// ---------------------------------------------------------------------------
// Kernel 5: output GEMM (split-K).  out[b,s,o] = sum_i y[b,s,i]*Wout[o,i]
// grid (4 n-tiles of 32, 4 K-splits of 256, 8 batches); writes g_part.
// ---------------------------------------------------------------------------
__global__ void outgemm_kernel(const float* __restrict__ Wout) {
    __shared__ float ys[64 * 128];
    __shared__ float ws[128 * 32];   // [k][n]
    int n0  = blockIdx.x * 32;
    int ksb = blockIdx.y;
    int b   = blockIdx.z;
    int tid = threadIdx.x;           // 256

    float acc[2][4];
#pragma unroll
    for (int mm = 0; mm < 2; mm++)
#pragma unroll
        for (int nn = 0; nn < 4; nn++) acc[mm][nn] = 0.f;

    for (int kc = 0; kc < 2; kc++) {
        int k0 = ksb * 256 + kc * 128;
        __syncthreads();
        for (int i = tid; i < 2048; i += 256) {    // ys: 64x128 floats
            int m = i >> 5, k4 = i & 31;
            reinterpret_cast<float4*>(ys)[i] =
                *reinterpret_cast<const float4*>(g_y + (size_t)(b * 64 + m) * 1024 + k0 + k4 * 4);
        }
        for (int i = tid; i < 1024; i += 256) {    // ws: 32 rows x 128 k (transposed)
            int n = i >> 5, k4 = i & 31;
            float4 w4 = *reinterpret_cast<const float4*>(Wout + (size_t)(n0 + n) * 1024 + k0 + k4 * 4);
            int k = k4 * 4;
            ws[(k + 0) * 32 + n] = w4.x;
            ws[(k + 1) * 32 + n] = w4.y;
            ws[(k + 2) * 32 + n] = w4.z;
            ws[(k + 3) * 32 + n] = w4.w;
        }
        __syncthreads();

        int ty = tid >> 3;   // 0..31 -> rows {ty, ty+32}
        int tx = tid & 7;    // 0..7  -> cols tx*4..+3
        for (int k = 0; k < 128; k++) {
            float4 b4 = reinterpret_cast<const float4*>(ws + k * 32)[tx];
            float a0 = ys[ty * 128 + k];
            float a1 = ys[(ty + 32) * 128 + k];
            acc[0][0] += a0 * b4.x; acc[0][1] += a0 * b4.y;
            acc[0][2] += a0 * b4.z; acc[0][3] += a0 * b4.w;
            acc[1][0] += a1 * b4.x; acc[1][1] += a1 * b4.y;
            acc[1][2] += a1 * b4.z; acc[1][3] += a1 * b4.w;
        }
    }

    int ty = tid >> 3, tx = tid & 7;
#pragma unroll
    for (int mm = 0; mm < 2; mm++) {
        int m = ty + mm * 32;
        float4 o = make_float4(acc[mm][0], acc[mm][1], acc[mm][2], acc[mm][3]);
        reinterpret_cast<float4*>(g_part + (size_t)ksb * 65536
                                  + (size_t)(b * 64 + m) * 128 + n0)[tx] = o;
    }
}

__global__ void reduce_kernel(float* __restrict__ out) {
    int i = blockIdx.x * 256 + threadIdx.x;
    out[i] = ((g_part[i] + g_part[65536 + i]) + g_part[131072 + i]) + g_part[196608 + i];
}

// ---------------------------------------------------------------------------
extern "C" void kernel_launch(void* const* d_in, const int* in_sizes, int n_in,
                              void* d_out, int out_size) {
    const float* x      = (const float*)d_in[0];
    const float* cosp   = (const float*)d_in[1];
    const float* sinp   = (const float*)d_in[2];
    const float* sink   = (const float*)d_in[3];
    const float* W_qkvg = (const float*)d_in[4];
    const float* patchw = (const float*)d_in[5];
    const float* W_out  = (const float*)d_in[6];
    const float* tao    = (const float*)d_in[7];
    float* out = (float*)d_out;

    const int smem3 = (64 * 128 + 128 * 128) * 4;                 // 96 KB
    const int smem4 = (3 * 65 * 129 + 65 * 66) * 4;               // ~118 KB
    cudaFuncSetAttribute(qkvg_kernel, cudaFuncAttributeMaxDynamicSharedMemorySize, smem3);
    cudaFuncSetAttribute(attn_kernel, cudaFuncAttributeMaxDynamicSharedMemorySize, smem4);

    patch_score_kernel<<<B_ * NP_, 256>>>(x, patchw);
    topk_kernel<<<B_, 32>>>();
    qkvg_kernel<<<dim3(32, B_), 256, smem3>>>(x, W_qkvg);
    attn_kernel<<<B_ * H_, 256, smem4>>>(cosp, sinp, sink, tao);
    outgemm_kernel<<<dim3(4, 4, B_), 256>>>(W_out);
    reduce_kernel<<<B_ * 64 * 128 / 256, 256>>>(out);
}

// round 2
// speedup vs baseline: 1.4746x; 1.4746x over previous
#include <cuda_runtime.h>
#include <cuda_bf16.h>
#include <math.h>

// Problem constants
#define B_   8
#define T_   8192
#define C_   128
#define H_   8
#define T0_  16
#define NP_  512           // T/T0
#define S_   65            // 4 patches * 16 + 1 sink
#define EPS_ 1.1920929e-07f

// Scratch (device globals; no allocation allowed)
__device__ float g_logits[B_ * NP_];             // 4096
__device__ int   g_topk[B_ * 4];                 // sorted patch indices per batch
__device__ float g_qkvg[B_ * 64 * 4096];         // 8 MB: qkvg for 64 selected tokens/batch
__device__ float g_y[B_ * 64 * 1024];            // 2 MB: gated attention output
__device__ float g_part[4 * B_ * 64 * 128];      // 1 MB: split-K partials of final GEMM

// ---------------------------------------------------------------------------
// Kernel 1: patch score logits.
// ---------------------------------------------------------------------------
__global__ void patch_score_kernel(const float* __restrict__ x,
                                   const float* __restrict__ pw) {
    int blk = blockIdx.x;                  // b*512 + p
    const float4* v = reinterpret_cast<const float4*>(x + (size_t)blk * 2048);
    const float4* w = reinterpret_cast<const float4*>(pw);
    float ssq = 0.f, dot = 0.f;
    for (int i = threadIdx.x; i < 512; i += 256) {
        float4 a = v[i];
        float4 b = w[i];
        ssq += a.x * a.x + a.y * a.y + a.z * a.z + a.w * a.w;
        dot += a.x * b.x + a.y * b.y + a.z * b.z + a.w * b.w;
    }
    for (int off = 16; off; off >>= 1) {
        ssq += __shfl_xor_sync(0xffffffffu, ssq, off);
        dot += __shfl_xor_sync(0xffffffffu, dot, off);
    }
    __shared__ float red[16];
    int wid = threadIdx.x >> 5, lane = threadIdx.x & 31;
    if (lane == 0) { red[wid] = ssq; red[8 + wid] = dot; }
    __syncthreads();
    if (threadIdx.x == 0) {
        float S = 0.f, D = 0.f;
        for (int wv = 0; wv < 8; wv++) { S += red[wv]; D += red[8 + wv]; }
        g_logits[blk] = D * rsqrtf(S * (1.0f / 2048.0f) + EPS_);
    }
}

// ---------------------------------------------------------------------------
// Kernel 2: top-4 per batch, sorted ascending. One warp per batch.
// ---------------------------------------------------------------------------
__global__ void topk_kernel() {
    int b = blockIdx.x;
    int lane = threadIdx.x;   // 32 threads
    float vals[16];
    for (int i = 0; i < 16; i++) vals[i] = g_logits[b * NP_ + lane * 16 + i];
    int chosen[4];
    for (int r = 0; r < 4; r++) {
        float best = -3.4e38f;
        int bi = 0x7fffffff;
        for (int i = 0; i < 16; i++) {
            int idx = lane * 16 + i;
            bool used = false;
            for (int j = 0; j < r; j++) if (chosen[j] == idx) used = true;
            if (!used && vals[i] > best) { best = vals[i]; bi = idx; }
        }
        for (int off = 16; off; off >>= 1) {
            float ov = __shfl_down_sync(0xffffffffu, best, off);
            int   oi = __shfl_down_sync(0xffffffffu, bi, off);
            if (ov > best || (ov == best && oi < bi)) { best = ov; bi = oi; }
        }
        bi = __shfl_sync(0xffffffffu, bi, 0);
        chosen[r] = bi;
    }
    if (lane == 0) {
        for (int i = 0; i < 3; i++)
            for (int j = i + 1; j < 4; j++)
                if (chosen[j] < chosen[i]) { int t = chosen[i]; chosen[i] = chosen[j]; chosen[j] = t; }
        for (int i = 0; i < 4; i++) g_topk[b * 4 + i] = chosen[i];
    }
}

// ---------------------------------------------------------------------------
// Kernel 3: qkvg projection for the 64 selected tokens of each batch.
// ---------------------------------------------------------------------------
__global__ void qkvg_kernel(const float* __restrict__ x,
                            const float* __restrict__ W) {
    extern __shared__ float sm3[];
    float* xs = sm3;            // 64*128
    float* ws = sm3 + 64 * 128; // 128*128, layout [k][n]
    int b  = blockIdx.y;
    int n0 = blockIdx.x * 128;
    int tid = threadIdx.x;      // 256

    for (int i = tid; i < 2048; i += 256) {
        int m  = i >> 5;
        int c4 = i & 31;
        int tok = g_topk[b * 4 + (m >> 4)] * T0_ + (m & 15);
        reinterpret_cast<float4*>(xs)[i] =
            reinterpret_cast<const float4*>(x + ((size_t)b * T_ + tok) * C_)[c4];
    }
    for (int i = tid; i < 4096; i += 256) {
        int n  = i >> 5;
        int k4 = i & 31;
        float4 wv = reinterpret_cast<const float4*>(W + (size_t)(n0 + n) * C_)[k4];
        int k = k4 * 4;
        ws[(k + 0) * 128 + n] = wv.x;
        ws[(k + 1) * 128 + n] = wv.y;
        ws[(k + 2) * 128 + n] = wv.z;
        ws[(k + 3) * 128 + n] = wv.w;
    }
    __syncthreads();

    int ty = tid >> 5;
    int tx = tid & 31;
    float acc[8][4];
#pragma unroll
    for (int mm = 0; mm < 8; mm++)
#pragma unroll
        for (int nn = 0; nn < 4; nn++) acc[mm][nn] = 0.f;

    for (int k = 0; k < 128; k++) {
        float4 bv = reinterpret_cast<const float4*>(ws + k * 128)[tx];
#pragma unroll
        for (int mm = 0; mm < 8; mm++) {
            float a = xs[(ty * 8 + mm) * 128 + k];
            acc[mm][0] += a * bv.x;
            acc[mm][1] += a * bv.y;
            acc[mm][2] += a * bv.z;
            acc[mm][3] += a * bv.w;
        }
    }
#pragma unroll
    for (int mm = 0; mm < 8; mm++) {
        int m = ty * 8 + mm;
        float4 o = make_float4(acc[mm][0], acc[mm][1], acc[mm][2], acc[mm][3]);
        reinterpret_cast<float4*>(g_qkvg + ((size_t)(b * 64 + m)) * 4096 + n0)[tx] = o;
    }
}

// ---------------------------------------------------------------------------
// Kernel 4 (REWRITTEN): attention per (b,h). 64 blocks x 256 threads.
// Stride 132 for q/k/v (float4-aligned, odd bank group), att stride 66.
// ---------------------------------------------------------------------------
__global__ void attn_kernel(const float* __restrict__ cosp,
                            const float* __restrict__ sinp,
                            const float* __restrict__ sink,
                            const float* __restrict__ tao) {
    extern __shared__ float sm4[];
    float* qs  = sm4;                      // 65*132
    float* ks_ = sm4 + 65 * 132;
    float* vs  = sm4 + 2 * 65 * 132;
    float* att = sm4 + 3 * 65 * 132;       // 65*66

    int b = blockIdx.x >> 3;
    int h = blockIdx.x & 7;
    int tid  = threadIdx.x;
    int warp = tid >> 5;
    int lane = tid & 31;
    float tao0 = tao[0], tao1 = tao[1];

    // zero att (upper triangle must be 0 for guard-free AV)
    for (int i = tid; i < 65 * 66; i += 256) att[i] = 0.f;

    // load + rope + rmsnorm q and k; raw copy v
    for (int s = warp; s < S_; s += 8) {
        const float* qsrc;
        const float* ksrc;
        const float* vsrc;
        if (s == 0) {
            qsrc = sink + h * C_;
            ksrc = qsrc;
            vsrc = qsrc;
        } else {
            int sp = s - 1;
            int j = sp >> 4, r = sp & 15;
            size_t base = (size_t)(b * 64 + j * 16) * 4096 + (size_t)(r & 3) * 1024 + h * C_;
            qsrc = g_qkvg + base + (size_t)((r >> 2) + 0) * 4096;
            ksrc = g_qkvg + base + (size_t)((r >> 2) + 4) * 4096;
            vsrc = g_qkvg + base + (size_t)((r >> 2) + 8) * 4096;
        }
        float c0 = cosp[s * 64 + lane],      s0 = sinp[s * 64 + lane];
        float c1 = cosp[s * 64 + lane + 32], s1 = sinp[s * 64 + lane + 32];

        {
            float a0 = qsrc[lane], a1 = qsrc[lane + 32], a2 = qsrc[lane + 64], a3 = qsrc[lane + 96];
            float o0 =  a0 * c0 + a2 * s0;
            float o2 = -a0 * s0 + a2 * c0;
            float o1 =  a1 * c1 + a3 * s1;
            float o3 = -a1 * s1 + a3 * c1;
            float ss = o0 * o0 + o1 * o1 + o2 * o2 + o3 * o3;
            for (int off = 16; off; off >>= 1) ss += __shfl_xor_sync(0xffffffffu, ss, off);
            float rn = rsqrtf(ss * (1.0f / 128.0f) + EPS_) * tao0;
            qs[s * 132 + lane]      = o0 * rn;
            qs[s * 132 + lane + 32] = o1 * rn;
            qs[s * 132 + lane + 64] = o2 * rn;
            qs[s * 132 + lane + 96] = o3 * rn;
        }
        {
            float a0 = ksrc[lane], a1 = ksrc[lane + 32], a2 = ksrc[lane + 64], a3 = ksrc[lane + 96];
            float o0 =  a0 * c0 + a2 * s0;
            float o2 = -a0 * s0 + a2 * c0;
            float o1 =  a1 * c1 + a3 * s1;
            float o3 = -a1 * s1 + a3 * c1;
            float ss = o0 * o0 + o1 * o1 + o2 * o2 + o3 * o3;
            for (int off = 16; off; off >>= 1) ss += __shfl_xor_sync(0xffffffffu, ss, off);
            float rn = rsqrtf(ss * (1.0f / 128.0f) + EPS_) * tao1;
            ks_[s * 132 + lane]      = o0 * rn;
            ks_[s * 132 + lane + 32] = o1 * rn;
            ks_[s * 132 + lane + 64] = o2 * rn;
            ks_[s * 132 + lane + 96] = o3 * rn;
        }
        vs[s * 132 + lane]      = vsrc[lane];
        vs[s * 132 + lane + 32] = vsrc[lane + 32];
        vs[s * 132 + lane + 64] = vsrc[lane + 64];
        vs[s * 132 + lane + 96] = vsrc[lane + 96];
    }
    __syncthreads();

    // ---- Score phase: warp-task = (4 query rows, 32 key cols) --------------
    const float scale = 0.08838834764831845f;  // 1/sqrt(128)
    for (int task = warp; task < 27; task += 8) {
        int tc, sg;
        if (task < 17)      { tc = 0; sg = task; }
        else if (task < 26) { tc = 1; sg = task - 9; }   // sg 8..16
        else                { tc = 2; sg = 16; }
        int t  = tc * 32 + lane;
        int te = (t < 64) ? t : 64;
        int s0 = sg * 4;
        int se0 = (s0 + 0 < 64) ? s0 + 0 : 64;
        int se1 = (s0 + 1 < 64) ? s0 + 1 : 64;
        int se2 = (s0 + 2 < 64) ? s0 + 2 : 64;
        int se3 = (s0 + 3 < 64) ? s0 + 3 : 64;

        const float4* kr = reinterpret_cast<const float4*>(ks_ + te * 132);
        const float4* q0 = reinterpret_cast<const float4*>(qs + se0 * 132);
        const float4* q1 = reinterpret_cast<const float4*>(qs + se1 * 132);
        const float4* q2 = reinterpret_cast<const float4*>(qs + se2 * 132);
        const float4* q3 = reinterpret_cast<const float4*>(qs + se3 * 132);

        float4 a0 = {0,0,0,0}, a1 = {0,0,0,0}, a2 = {0,0,0,0}, a3 = {0,0,0,0};
#pragma unroll 8
        for (int c4 = 0; c4 < 32; c4++) {
            float4 kv = kr[c4];
            float4 v0 = q0[c4];
            a0.x += v0.x * kv.x; a0.y += v0.y * kv.y; a0.z += v0.z * kv.z; a0.w += v0.w * kv.w;
            float4 v1 = q1[c4];
            a1.x += v1.x * kv.x; a1.y += v1.y * kv.y; a1.z += v1.z * kv.z; a1.w += v1.w * kv.w;
            float4 v2 = q2[c4];
            a2.x += v2.x * kv.x; a2.y += v2.y * kv.y; a2.z += v2.z * kv.z; a2.w += v2.w * kv.w;
            float4 v3 = q3[c4];
            a3.x += v3.x * kv.x; a3.y += v3.y * kv.y; a3.z += v3.z * kv.z; a3.w += v3.w * kv.w;
        }
        float r0 = (a0.x + a0.y) + (a0.z + a0.w);
        float r1 = (a1.x + a1.y) + (a1.z + a1.w);
        float r2 = (a2.x + a2.y) + (a2.z + a2.w);
        float r3 = (a3.x + a3.y) + (a3.z + a3.w);
        if (t <= 64) {
            if (s0 + 0 <= 64 && t <= s0 + 0) att[(s0 + 0) * 66 + t] = r0 * scale;
            if (s0 + 1 <= 64 && t <= s0 + 1) att[(s0 + 1) * 66 + t] = r1 * scale;
            if (s0 + 2 <= 64 && t <= s0 + 2) att[(s0 + 2) * 66 + t] = r2 * scale;
            if (s0 + 3 <= 64 && t <= s0 + 3) att[(s0 + 3) * 66 + t] = r3 * scale;
        }
    }
    __syncthreads();

    // ---- Softmax: one warp per row, lanes parallel over t ------------------
    for (int s = warp; s < S_; s += 8) {
        float v0 = (lane      <= s) ? att[s * 66 + lane]      : -3.4e38f;
        float v1 = (lane + 32 <= s) ? att[s * 66 + lane + 32] : -3.4e38f;
        float v2 = (lane + 64 <= s) ? att[s * 66 + lane + 64] : -3.4e38f;
        float m = fmaxf(fmaxf(v0, v1), v2);
        for (int off = 16; off; off >>= 1) m = fmaxf(m, __shfl_xor_sync(0xffffffffu, m, off));
        float e0 = (lane      <= s) ? __expf(v0 - m) : 0.f;
        float e1 = (lane + 32 <= s) ? __expf(v1 - m) : 0.f;
        float e2 = (lane + 64 <= s) ? __expf(v2 - m) : 0.f;
        float sum = e0 + e1 + e2;
        for (int off = 16; off; off >>= 1) sum += __shfl_xor_sync(0xffffffffu, sum, off);
        float inv = 1.f / sum;
        if (lane      <= s) att[s * 66 + lane]      = e0 * inv;
        if (lane + 32 <= s) att[s * 66 + lane + 32] = e1 * inv;
        if (lane + 64 <= s) att[s * 66 + lane + 64] = e2 * inv;
    }
    __syncthreads();

    // ---- AV phase: warp owns 8 output rows, lane owns one float4 of c ------
    {
        int grp = (warp < 4) ? warp : 11 - warp;   // SMSP load balancing
        int sp0 = grp * 8;
        float4 acc[8];
#pragma unroll
        for (int j = 0; j < 8; j++) acc[j] = make_float4(0.f, 0.f, 0.f, 0.f);
        int tmax = sp0 + 8;                        // max s in this row group
        for (int t = 0; t <= tmax; t++) {
            float4 vv = *reinterpret_cast<const float4*>(vs + t * 132 + lane * 4);
#pragma unroll
            for (int j = 0; j < 8; j++) {
                float a = att[(sp0 + j + 1) * 66 + t];   // 0 for t > s
                acc[j].x += a * vv.x;
                acc[j].y += a * vv.y;
                acc[j].z += a * vv.z;
                acc[j].w += a * vv.w;
            }
        }
#pragma unroll
        for (int j = 0; j < 8; j++) {
            int sp = sp0 + j;
            int jp = sp >> 4, r = sp & 15;
            const float* gp = g_qkvg + (size_t)(b * 64 + jp * 16 + 12 + (r >> 2)) * 4096
                              + (size_t)(r & 3) * 1024 + h * C_ + lane * 4;
            float4 gv = *reinterpret_cast<const float4*>(gp);
            float4 o;
            o.x = acc[j].x / (1.f + __expf(-gv.x));
            o.y = acc[j].y / (1.f + __expf(-gv.y));
            o.z = acc[j].z / (1.f + __expf(-gv.z));
            o.w = acc[j].w / (1.f + __expf(-gv.w));
            *reinterpret_cast<float4*>(g_y + (size_t)(b * 64 + sp) * 1024 + h * C_ + lane * 4) = o;
        }
    }
}

// ---------------------------------------------------------------------------
// Kernel 5: output GEMM (split-K).
// ---------------------------------------------------------------------------
__global__ void outgemm_kernel(const float* __restrict__ Wout) {
    __shared__ float ys[64 * 128];
    __shared__ float ws[128 * 32];   // [k][n]
    int n0  = blockIdx.x * 32;
    int ksb = blockIdx.y;
    int b   = blockIdx.z;
    int tid = threadIdx.x;           // 256

    float acc[2][4];
#pragma unroll
    for (int mm = 0; mm < 2; mm++)
#pragma unroll
        for (int nn = 0; nn < 4; nn++) acc[mm][nn] = 0.f;

    for (int kc = 0; kc < 2; kc++) {
        int k0 = ksb * 256 + kc * 128;
        __syncthreads();
        for (int i = tid; i < 2048; i += 256) {
            int m = i >> 5, k4 = i & 31;
            reinterpret_cast<float4*>(ys)[i] =
                *reinterpret_cast<const float4*>(g_y + (size_t)(b * 64 + m) * 1024 + k0 + k4 * 4);
        }
        for (int i = tid; i < 1024; i += 256) {
            int n = i >> 5, k4 = i & 31;
            float4 w4 = *reinterpret_cast<const float4*>(Wout + (size_t)(n0 + n) * 1024 + k0 + k4 * 4);
            int k = k4 * 4;
            ws[(k + 0) * 32 + n] = w4.x;
            ws[(k + 1) * 32 + n] = w4.y;
            ws[(k + 2) * 32 + n] = w4.z;
            ws[(k + 3) * 32 + n] = w4.w;
        }
        __syncthreads();

        int ty = tid >> 3;
        int tx = tid & 7;
        for (int k = 0; k < 128; k++) {
            float4 b4 = reinterpret_cast<const float4*>(ws + k * 32)[tx];
            float a0 = ys[ty * 128 + k];
            float a1 = ys[(ty + 32) * 128 + k];
            acc[0][0] += a0 * b4.x; acc[0][1] += a0 * b4.y;
            acc[0][2] += a0 * b4.z; acc[0][3] += a0 * b4.w;
            acc[1][0] += a1 * b4.x; acc[1][1] += a1 * b4.y;
            acc[1][2] += a1 * b4.z; acc[1][3] += a1 * b4.w;
        }
    }

    int ty = tid >> 3, tx = tid & 7;
#pragma unroll
    for (int mm = 0; mm < 2; mm++) {
        int m = ty + mm * 32;
        float4 o = make_float4(acc[mm][0], acc[mm][1], acc[mm][2], acc[mm][3]);
        reinterpret_cast<float4*>(g_part + (size_t)ksb * 65536
                                  + (size_t)(b * 64 + m) * 128 + n0)[tx] = o;
    }
}

__global__ void reduce_kernel(float* __restrict__ out) {
    int i = blockIdx.x * 256 + threadIdx.x;
    out[i] = ((g_part[i] + g_part[65536 + i]) + g_part[131072 + i]) + g_part[196608 + i];
}

// ---------------------------------------------------------------------------
extern "C" void kernel_launch(void* const* d_in, const int* in_sizes, int n_in,
                              void* d_out, int out_size) {
    const float* x      = (const float*)d_in[0];
    const float* cosp   = (const float*)d_in[1];
    const float* sinp   = (const float*)d_in[2];
    const float* sink   = (const float*)d_in[3];
    const float* W_qkvg = (const float*)d_in[4];
    const float* patchw = (const float*)d_in[5];
    const float* W_out  = (const float*)d_in[6];
    const float* tao    = (const float*)d_in[7];
    float* out = (float*)d_out;

    const int smem3 = (64 * 128 + 128 * 128) * 4;                 // 96 KB
    const int smem4 = (3 * 65 * 132 + 65 * 66) * 4;               // ~120 KB
    cudaFuncSetAttribute(qkvg_kernel, cudaFuncAttributeMaxDynamicSharedMemorySize, smem3);
    cudaFuncSetAttribute(attn_kernel, cudaFuncAttributeMaxDynamicSharedMemorySize, smem4);

    patch_score_kernel<<<B_ * NP_, 256>>>(x, patchw);
    topk_kernel<<<B_, 32>>>();
    qkvg_kernel<<<dim3(32, B_), 256, smem3>>>(x, W_qkvg);
    attn_kernel<<<B_ * H_, 256, smem4>>>(cosp, sinp, sink, tao);
    outgemm_kernel<<<dim3(4, 4, B_), 256>>>(W_out);
    reduce_kernel<<<B_ * 64 * 128 / 256, 256>>>(out);
}

// round 4
// speedup vs baseline: 1.6224x; 1.1002x over previous
#include <cuda_runtime.h>
#include <cuda_bf16.h>
#include <math.h>

// Problem constants
#define B_   8
#define T_   8192
#define C_   128
#define H_   8
#define T0_  16
#define NP_  512           // T/T0
#define S_   65            // 4 patches * 16 + 1 sink
#define EPS_ 1.1920929e-07f

// Scratch (device globals; no allocation allowed)
__device__ float g_logits[B_ * NP_];             // 4096
__device__ int   g_topk[B_ * 4];                 // sorted patch indices per batch
__device__ float g_qkvg[B_ * 64 * 4096];         // 8 MB
__device__ float g_y[B_ * 64 * 1024];            // 2 MB
__device__ float g_part[4 * B_ * 64 * 128];      // 1 MB

// Packed fp32 pair FMA: d = a*b + d (both lanes)
__device__ __forceinline__ void ffma2(float2& d, float2 a, float2 b) {
    asm("fma.rn.f32x2 %0, %1, %2, %0;"
        : "+l"(reinterpret_cast<unsigned long long&>(d))
        : "l"(reinterpret_cast<unsigned long long&>(a)),
          "l"(reinterpret_cast<unsigned long long&>(b)));
}

// ---------------------------------------------------------------------------
// Kernel 1: patch score logits.
// ---------------------------------------------------------------------------
__global__ void patch_score_kernel(const float* __restrict__ x,
                                   const float* __restrict__ pw) {
    int blk = blockIdx.x;                  // b*512 + p
    const float4* v = reinterpret_cast<const float4*>(x + (size_t)blk * 2048);
    const float4* w = reinterpret_cast<const float4*>(pw);
    float ssq = 0.f, dot = 0.f;
    for (int i = threadIdx.x; i < 512; i += 256) {
        float4 a = v[i];
        float4 b = w[i];
        ssq += a.x * a.x + a.y * a.y + a.z * a.z + a.w * a.w;
        dot += a.x * b.x + a.y * b.y + a.z * b.z + a.w * b.w;
    }
    for (int off = 16; off; off >>= 1) {
        ssq += __shfl_xor_sync(0xffffffffu, ssq, off);
        dot += __shfl_xor_sync(0xffffffffu, dot, off);
    }
    __shared__ float red[16];
    int wid = threadIdx.x >> 5, lane = threadIdx.x & 31;
    if (lane == 0) { red[wid] = ssq; red[8 + wid] = dot; }
    __syncthreads();
    if (threadIdx.x == 0) {
        float S = 0.f, D = 0.f;
        for (int wv = 0; wv < 8; wv++) { S += red[wv]; D += red[8 + wv]; }
        g_logits[blk] = D * rsqrtf(S * (1.0f / 2048.0f) + EPS_);
    }
}

// ---------------------------------------------------------------------------
// Kernel 2: top-4 per batch, sorted ascending. One warp per batch.
// ---------------------------------------------------------------------------
__global__ void topk_kernel() {
    int b = blockIdx.x;
    int lane = threadIdx.x;   // 32 threads
    float vals[16];
    for (int i = 0; i < 16; i++) vals[i] = g_logits[b * NP_ + lane * 16 + i];
    int chosen[4];
    for (int r = 0; r < 4; r++) {
        float best = -3.4e38f;
        int bi = 0x7fffffff;
        for (int i = 0; i < 16; i++) {
            int idx = lane * 16 + i;
            bool used = false;
            for (int j = 0; j < r; j++) if (chosen[j] == idx) used = true;
            if (!used && vals[i] > best) { best = vals[i]; bi = idx; }
        }
        for (int off = 16; off; off >>= 1) {
            float ov = __shfl_down_sync(0xffffffffu, best, off);
            int   oi = __shfl_down_sync(0xffffffffu, bi, off);
            if (ov > best || (ov == best && oi < bi)) { best = ov; bi = oi; }
        }
        bi = __shfl_sync(0xffffffffu, bi, 0);
        chosen[r] = bi;
    }
    if (lane == 0) {
        for (int i = 0; i < 3; i++)
            for (int j = i + 1; j < 4; j++)
                if (chosen[j] < chosen[i]) { int t = chosen[i]; chosen[i] = chosen[j]; chosen[j] = t; }
        for (int i = 0; i < 4; i++) g_topk[b * 4 + i] = chosen[i];
    }
}

// ---------------------------------------------------------------------------
// Kernel 3: qkvg projection. f32x2 pairs over n (b-side float4 = 2 n-pairs,
// a-side scalar broadcast packed into (a,a)).
// ---------------------------------------------------------------------------
__global__ void qkvg_kernel(const float* __restrict__ x,
                            const float* __restrict__ W) {
    extern __shared__ float sm3[];
    float* xs = sm3;            // 64*128
    float* ws = sm3 + 64 * 128; // 128*128, layout [k][n]
    int b  = blockIdx.y;
    int n0 = blockIdx.x * 128;
    int tid = threadIdx.x;      // 256

    for (int i = tid; i < 2048; i += 256) {
        int m  = i >> 5;
        int c4 = i & 31;
        int tok = g_topk[b * 4 + (m >> 4)] * T0_ + (m & 15);
        reinterpret_cast<float4*>(xs)[i] =
            reinterpret_cast<const float4*>(x + ((size_t)b * T_ + tok) * C_)[c4];
    }
    for (int i = tid; i < 4096; i += 256) {
        int n  = i >> 5;
        int k4 = i & 31;
        float4 wv = reinterpret_cast<const float4*>(W + (size_t)(n0 + n) * C_)[k4];
        int k = k4 * 4;
        ws[(k + 0) * 128 + n] = wv.x;
        ws[(k + 1) * 128 + n] = wv.y;
        ws[(k + 2) * 128 + n] = wv.z;
        ws[(k + 3) * 128 + n] = wv.w;
    }
    __syncthreads();

    int ty = tid >> 5;   // 0..7 -> rows ty*8..ty*8+7
    int tx = tid & 31;   // cols tx*4..tx*4+3
    float2 acc2[8][2];
#pragma unroll
    for (int mm = 0; mm < 8; mm++) {
        acc2[mm][0] = make_float2(0.f, 0.f);
        acc2[mm][1] = make_float2(0.f, 0.f);
    }

#pragma unroll 4
    for (int k = 0; k < 128; k++) {
        float4 bv = reinterpret_cast<const float4*>(ws + k * 128)[tx];
        float2 bp0 = make_float2(bv.x, bv.y);
        float2 bp1 = make_float2(bv.z, bv.w);
#pragma unroll
        for (int mm = 0; mm < 8; mm++) {
            float a = xs[(ty * 8 + mm) * 128 + k];
            float2 ap = make_float2(a, a);
            ffma2(acc2[mm][0], ap, bp0);
            ffma2(acc2[mm][1], ap, bp1);
        }
    }
#pragma unroll
    for (int mm = 0; mm < 8; mm++) {
        int m = ty * 8 + mm;
        float4 o = make_float4(acc2[mm][0].x, acc2[mm][0].y, acc2[mm][1].x, acc2[mm][1].y);
        reinterpret_cast<float4*>(g_qkvg + ((size_t)(b * 64 + m)) * 4096 + n0)[tx] = o;
    }
}

// ---------------------------------------------------------------------------
// Kernel 4: attention. 128 blocks (2 per (b,h)), parity split over query rows.
// half=0 -> s even (33 rows incl sink), half=1 -> s odd (32 rows).
// ---------------------------------------------------------------------------
__global__ void attn_kernel(const float* __restrict__ cosp,
                            const float* __restrict__ sinp,
                            const float* __restrict__ sink,
                            const float* __restrict__ tao) {
    extern __shared__ float sm4[];
    float* qs  = sm4;                        // 33*132 (own query rows)
    float* ks_ = sm4 + 33 * 132;             // 65*132
    float* vs  = ks_ + 65 * 132;             // 65*132
    float* att = vs + 65 * 132;              // 33*66

    int blk  = blockIdx.x;
    int bh   = blk >> 1;
    int half = blk & 1;
    int b = bh >> 3;
    int h = bh & 7;
    int nrows = 33 - half;                   // 33 or 32
    int tid  = threadIdx.x;
    int warp = tid >> 5;
    int lane = tid & 31;
    float tao0 = tao[0], tao1 = tao[1];

    // zero att (upper triangle must be 0 for guard-free AV)
    for (int i = tid; i < 33 * 66; i += 256) att[i] = 0.f;

    // prep: k,v for all 65 rows; q only for own-parity rows
    for (int s = warp; s < S_; s += 8) {
        const float* qsrc;
        const float* ksrc;
        const float* vsrc;
        if (s == 0) {
            qsrc = sink + h * C_;
            ksrc = qsrc;
            vsrc = qsrc;
        } else {
            int sp = s - 1;
            int j = sp >> 4, r = sp & 15;
            size_t base = (size_t)(b * 64 + j * 16) * 4096 + (size_t)(r & 3) * 1024 + h * C_;
            qsrc = g_qkvg + base + (size_t)((r >> 2) + 0) * 4096;
            ksrc = g_qkvg + base + (size_t)((r >> 2) + 4) * 4096;
            vsrc = g_qkvg + base + (size_t)((r >> 2) + 8) * 4096;
        }
        float c0 = cosp[s * 64 + lane],      s0 = sinp[s * 64 + lane];
        float c1 = cosp[s * 64 + lane + 32], s1 = sinp[s * 64 + lane + 32];

        // k (always)
        {
            float a0 = ksrc[lane], a1 = ksrc[lane + 32], a2 = ksrc[lane + 64], a3 = ksrc[lane + 96];
            float o0 =  a0 * c0 + a2 * s0;
            float o2 = -a0 * s0 + a2 * c0;
            float o1 =  a1 * c1 + a3 * s1;
            float o3 = -a1 * s1 + a3 * c1;
            float ss = o0 * o0 + o1 * o1 + o2 * o2 + o3 * o3;
            for (int off = 16; off; off >>= 1) ss += __shfl_xor_sync(0xffffffffu, ss, off);
            float rn = rsqrtf(ss * (1.0f / 128.0f) + EPS_) * tao1;
            ks_[s * 132 + lane]      = o0 * rn;
            ks_[s * 132 + lane + 32] = o1 * rn;
            ks_[s * 132 + lane + 64] = o2 * rn;
            ks_[s * 132 + lane + 96] = o3 * rn;
        }
        // v (always)
        vs[s * 132 + lane]      = vsrc[lane];
        vs[s * 132 + lane + 32] = vsrc[lane + 32];
        vs[s * 132 + lane + 64] = vsrc[lane + 64];
        vs[s * 132 + lane + 96] = vsrc[lane + 96];
        // q (own parity only)
        if ((s & 1) == half) {
            int i = s >> 1;
            float a0 = qsrc[lane], a1 = qsrc[lane + 32], a2 = qsrc[lane + 64], a3 = qsrc[lane + 96];
            float o0 =  a0 * c0 + a2 * s0;
            float o2 = -a0 * s0 + a2 * c0;
            float o1 =  a1 * c1 + a3 * s1;
            float o3 = -a1 * s1 + a3 * c1;
            float ss = o0 * o0 + o1 * o1 + o2 * o2 + o3 * o3;
            for (int off = 16; off; off >>= 1) ss += __shfl_xor_sync(0xffffffffu, ss, off);
            float rn = rsqrtf(ss * (1.0f / 128.0f) + EPS_) * tao0;
            qs[i * 132 + lane]      = o0 * rn;
            qs[i * 132 + lane + 32] = o1 * rn;
            qs[i * 132 + lane + 64] = o2 * rn;
            qs[i * 132 + lane + 96] = o3 * rn;
        }
    }
    __syncthreads();

    // ---- Score phase: task = (group of 4 own rows, 32-key chunk) -----------
    const float scale = 0.08838834764831845f;  // 1/sqrt(128)
    int ngroups = (nrows + 3) >> 2;
    for (int task = warp; task < ngroups * 3; task += 8) {
        int g = task / 3;
        int c = task - g * 3;
        int i0 = g * 4;
        int imax = min(i0 + 3, nrows - 1);
        int smax = 2 * imax + half;
        int t0 = c * 32;
        if (t0 > smax) continue;
        int t  = t0 + lane;
        int te = (t < 64) ? t : 64;
        int ie0 = min(i0 + 0, nrows - 1);
        int ie1 = min(i0 + 1, nrows - 1);
        int ie2 = min(i0 + 2, nrows - 1);
        int ie3 = min(i0 + 3, nrows - 1);

        const float4* kr = reinterpret_cast<const float4*>(ks_ + te * 132);
        const float4* q0 = reinterpret_cast<const float4*>(qs + ie0 * 132);
        const float4* q1 = reinterpret_cast<const float4*>(qs + ie1 * 132);
        const float4* q2 = reinterpret_cast<const float4*>(qs + ie2 * 132);
        const float4* q3 = reinterpret_cast<const float4*>(qs + ie3 * 132);

        float2 p00 = {0,0}, p01 = {0,0}, p10 = {0,0}, p11 = {0,0};
        float2 p20 = {0,0}, p21 = {0,0}, p30 = {0,0}, p31 = {0,0};
#pragma unroll 8
        for (int c4 = 0; c4 < 32; c4++) {
            float4 kv = kr[c4];
            float2 k0 = make_float2(kv.x, kv.y);
            float2 k1 = make_float2(kv.z, kv.w);
            float4 v0 = q0[c4];
            ffma2(p00, make_float2(v0.x, v0.y), k0);
            ffma2(p01, make_float2(v0.z, v0.w), k1);
            float4 v1 = q1[c4];
            ffma2(p10, make_float2(v1.x, v1.y), k0);
            ffma2(p11, make_float2(v1.z, v1.w), k1);
            float4 v2 = q2[c4];
            ffma2(p20, make_float2(v2.x, v2.y), k0);
            ffma2(p21, make_float2(v2.z, v2.w), k1);
            float4 v3 = q3[c4];
            ffma2(p30, make_float2(v3.x, v3.y), k0);
            ffma2(p31, make_float2(v3.z, v3.w), k1);
        }
        float r0 = (p00.x + p00.y) + (p01.x + p01.y);
        float r1 = (p10.x + p10.y) + (p11.x + p11.y);
        float r2 = (p20.x + p20.y) + (p21.x + p21.y);
        float r3 = (p30.x + p30.y) + (p31.x + p31.y);
        int s0v = 2 * (i0 + 0) + half;
        int s1v = 2 * (i0 + 1) + half;
        int s2v = 2 * (i0 + 2) + half;
        int s3v = 2 * (i0 + 3) + half;
        if (i0 + 0 < nrows && t <= s0v) att[(i0 + 0) * 66 + t] = r0 * scale;
        if (i0 + 1 < nrows && t <= s1v) att[(i0 + 1) * 66 + t] = r1 * scale;
        if (i0 + 2 < nrows && t <= s2v) att[(i0 + 2) * 66 + t] = r2 * scale;
        if (i0 + 3 < nrows && t <= s3v) att[(i0 + 3) * 66 + t] = r3 * scale;
    }
    __syncthreads();

    // ---- Softmax: one warp per own row ------------------------------------
    for (int i = warp; i < nrows; i += 8) {
        int s = 2 * i + half;
        float v0 = (lane      <= s) ? att[i * 66 + lane]      : -3.4e38f;
        float v1 = (lane + 32 <= s) ? att[i * 66 + lane + 32] : -3.4e38f;
        float v2 = (lane + 64 <= s) ? att[i * 66 + lane + 64] : -3.4e38f;
        float m = fmaxf(fmaxf(v0, v1), v2);
        for (int off = 16; off; off >>= 1) m = fmaxf(m, __shfl_xor_sync(0xffffffffu, m, off));
        float e0 = (lane      <= s) ? __expf(v0 - m) : 0.f;
        float e1 = (lane + 32 <= s) ? __expf(v1 - m) : 0.f;
        float e2 = (lane + 64 <= s) ? __expf(v2 - m) : 0.f;
        float sum = e0 + e1 + e2;
        for (int off = 16; off; off >>= 1) sum += __shfl_xor_sync(0xffffffffu, sum, off);
        float inv = 1.f / sum;
        if (lane      <= s) att[i * 66 + lane]      = e0 * inv;
        if (lane + 32 <= s) att[i * 66 + lane + 32] = e1 * inv;
        if (lane + 64 <= s) att[i * 66 + lane + 64] = e2 * inv;
    }
    __syncthreads();

    // ---- AV phase: warp owns rows i = warp + 8*jj -------------------------
    {
        int nj = (nrows - warp + 7) >> 3;        // 4 or 5
        int ilast = warp + 8 * (nj - 1);
        int tmax = 2 * ilast + half;
        float2 accp[5][2];
#pragma unroll
        for (int jj = 0; jj < 5; jj++) {
            accp[jj][0] = make_float2(0.f, 0.f);
            accp[jj][1] = make_float2(0.f, 0.f);
        }
        for (int t = 0; t <= tmax; t++) {
            float4 vv = *reinterpret_cast<const float4*>(vs + t * 132 + lane * 4);
            float2 vp0 = make_float2(vv.x, vv.y);
            float2 vp1 = make_float2(vv.z, vv.w);
#pragma unroll
            for (int jj = 0; jj < 5; jj++) {
                if (jj < nj) {
                    float a = att[(warp + 8 * jj) * 66 + t];   // 0 for t > s
                    float2 ap = make_float2(a, a);
                    ffma2(accp[jj][0], ap, vp0);
                    ffma2(accp[jj][1], ap, vp1);
                }
            }
        }
#pragma unroll
        for (int jj = 0; jj < 5; jj++) {
            if (jj < nj) {
                int i = warp + 8 * jj;
                int s = 2 * i + half;
                if (s == 0) continue;
                int sp = s - 1;
                int jp = sp >> 4, r = sp & 15;
                const float* gp = g_qkvg + (size_t)(b * 64 + jp * 16 + 12 + (r >> 2)) * 4096
                                  + (size_t)(r & 3) * 1024 + h * C_ + lane * 4;
                float4 gv = *reinterpret_cast<const float4*>(gp);
                float4 o;
                o.x = accp[jj][0].x / (1.f + __expf(-gv.x));
                o.y = accp[jj][0].y / (1.f + __expf(-gv.y));
                o.z = accp[jj][1].x / (1.f + __expf(-gv.z));
                o.w = accp[jj][1].y / (1.f + __expf(-gv.w));
                *reinterpret_cast<float4*>(g_y + (size_t)(b * 64 + sp) * 1024 + h * C_ + lane * 4) = o;
            }
        }
    }
}

// ---------------------------------------------------------------------------
// Kernel 5: output GEMM (split-K), f32x2 pairs over n.
// ---------------------------------------------------------------------------
__global__ void outgemm_kernel(const float* __restrict__ Wout) {
    __shared__ float ys[64 * 128];
    __shared__ float ws[128 * 32];   // [k][n]
    int n0  = blockIdx.x * 32;
    int ksb = blockIdx.y;
    int b   = blockIdx.z;
    int tid = threadIdx.x;           // 256

    float2 acc2[2][2];
#pragma unroll
    for (int mm = 0; mm < 2; mm++) {
        acc2[mm][0] = make_float2(0.f, 0.f);
        acc2[mm][1] = make_float2(0.f, 0.f);
    }

    for (int kc = 0; kc < 2; kc++) {
        int k0 = ksb * 256 + kc * 128;
        __syncthreads();
        for (int i = tid; i < 2048; i += 256) {
            int m = i >> 5, k4 = i & 31;
            reinterpret_cast<float4*>(ys)[i] =
                *reinterpret_cast<const float4*>(g_y + (size_t)(b * 64 + m) * 1024 + k0 + k4 * 4);
        }
        for (int i = tid; i < 1024; i += 256) {
            int n = i >> 5, k4 = i & 31;
            float4 w4 = *reinterpret_cast<const float4*>(Wout + (size_t)(n0 + n) * 1024 + k0 + k4 * 4);
            int k = k4 * 4;
            ws[(k + 0) * 32 + n] = w4.x;
            ws[(k + 1) * 32 + n] = w4.y;
            ws[(k + 2) * 32 + n] = w4.z;
            ws[(k + 3) * 32 + n] = w4.w;
        }
        __syncthreads();

        int ty = tid >> 3;   // rows {ty, ty+32}
        int tx = tid & 7;    // cols tx*4..+3
#pragma unroll 4
        for (int k = 0; k < 128; k++) {
            float4 b4 = reinterpret_cast<const float4*>(ws + k * 32)[tx];
            float2 bp0 = make_float2(b4.x, b4.y);
            float2 bp1 = make_float2(b4.z, b4.w);
            float a0 = ys[ty * 128 + k];
            float a1 = ys[(ty + 32) * 128 + k];
            float2 ap0 = make_float2(a0, a0);
            float2 ap1 = make_float2(a1, a1);
            ffma2(acc2[0][0], ap0, bp0);
            ffma2(acc2[0][1], ap0, bp1);
            ffma2(acc2[1][0], ap1, bp0);
            ffma2(acc2[1][1], ap1, bp1);
        }
    }

    int ty = tid >> 3, tx = tid & 7;
#pragma unroll
    for (int mm = 0; mm < 2; mm++) {
        int m = ty + mm * 32;
        float4 o = make_float4(acc2[mm][0].x, acc2[mm][0].y, acc2[mm][1].x, acc2[mm][1].y);
        reinterpret_cast<float4*>(g_part + (size_t)ksb * 65536
                                  + (size_t)(b * 64 + m) * 128 + n0)[tx] = o;
    }
}

__global__ void reduce_kernel(float* __restrict__ out) {
    int i = blockIdx.x * 256 + threadIdx.x;
    out[i] = ((g_part[i] + g_part[65536 + i]) + g_part[131072 + i]) + g_part[196608 + i];
}

// ---------------------------------------------------------------------------
extern "C" void kernel_launch(void* const* d_in, const int* in_sizes, int n_in,
                              void* d_out, int out_size) {
    const float* x      = (const float*)d_in[0];
    const float* cosp   = (const float*)d_in[1];
    const float* sinp   = (const float*)d_in[2];
    const float* sink   = (const float*)d_in[3];
    const float* W_qkvg = (const float*)d_in[4];
    const float* patchw = (const float*)d_in[5];
    const float* W_out  = (const float*)d_in[6];
    const float* tao    = (const float*)d_in[7];
    float* out = (float*)d_out;

    const int smem3 = (64 * 128 + 128 * 128) * 4;                       // 96 KB
    const int smem4 = (33 * 132 + 2 * 65 * 132 + 33 * 66) * 4;          // ~93 KB
    cudaFuncSetAttribute(qkvg_kernel, cudaFuncAttributeMaxDynamicSharedMemorySize, smem3);
    cudaFuncSetAttribute(attn_kernel, cudaFuncAttributeMaxDynamicSharedMemorySize, smem4);

    patch_score_kernel<<<B_ * NP_, 256>>>(x, patchw);
    topk_kernel<<<B_, 32>>>();
    qkvg_kernel<<<dim3(32, B_), 256, smem3>>>(x, W_qkvg);
    attn_kernel<<<B_ * H_ * 2, 256, smem4>>>(cosp, sinp, sink, tao);
    outgemm_kernel<<<dim3(4, 4, B_), 256>>>(W_out);
    reduce_kernel<<<B_ * 64 * 128 / 256, 256>>>(out);
}

// round 6
// speedup vs baseline: 1.7601x; 1.0848x over previous
#include <cuda_runtime.h>
#include <cuda_bf16.h>
#include <math.h>

// Problem constants
#define B_   8
#define T_   8192
#define C_   128
#define H_   8
#define T0_  16
#define NP_  512           // T/T0
#define S_   65            // 4 patches * 16 + 1 sink
#define EPS_ 1.1920929e-07f

// Scratch (device globals; no allocation allowed)
__device__ float g_logits[B_ * NP_];             // 4096
__device__ int   g_topk[B_ * 4];                 // sorted patch indices per batch
__device__ float g_qkvg[B_ * 64 * 4096];         // 8 MB
__device__ float g_y[B_ * 64 * 1024];            // 2 MB
__device__ float g_part[4 * B_ * 64 * 128];      // 1 MB

// Packed fp32 pair FMA: d = a*b + d (both lanes)
__device__ __forceinline__ void ffma2(float2& d, float2 a, float2 b) {
    asm("fma.rn.f32x2 %0, %1, %2, %0;"
        : "+l"(reinterpret_cast<unsigned long long&>(d))
        : "l"(reinterpret_cast<unsigned long long&>(a)),
          "l"(reinterpret_cast<unsigned long long&>(b)));
}

// ---------------------------------------------------------------------------
// Kernel 1: patch score logits.
// ---------------------------------------------------------------------------
__global__ void patch_score_kernel(const float* __restrict__ x,
                                   const float* __restrict__ pw) {
    int blk = blockIdx.x;                  // b*512 + p
    const float4* v = reinterpret_cast<const float4*>(x + (size_t)blk * 2048);
    const float4* w = reinterpret_cast<const float4*>(pw);
    float ssq = 0.f, dot = 0.f;
    for (int i = threadIdx.x; i < 512; i += 256) {
        float4 a = v[i];
        float4 b = w[i];
        ssq += a.x * a.x + a.y * a.y + a.z * a.z + a.w * a.w;
        dot += a.x * b.x + a.y * b.y + a.z * b.z + a.w * b.w;
    }
    for (int off = 16; off; off >>= 1) {
        ssq += __shfl_xor_sync(0xffffffffu, ssq, off);
        dot += __shfl_xor_sync(0xffffffffu, dot, off);
    }
    __shared__ float red[16];
    int wid = threadIdx.x >> 5, lane = threadIdx.x & 31;
    if (lane == 0) { red[wid] = ssq; red[8 + wid] = dot; }
    __syncthreads();
    if (threadIdx.x == 0) {
        float S = 0.f, D = 0.f;
        for (int wv = 0; wv < 8; wv++) { S += red[wv]; D += red[8 + wv]; }
        g_logits[blk] = D * rsqrtf(S * (1.0f / 2048.0f) + EPS_);
    }
}

// ---------------------------------------------------------------------------
// Kernel 2: top-4 per batch, sorted ascending. One warp per batch.
// ---------------------------------------------------------------------------
__global__ void topk_kernel() {
    int b = blockIdx.x;
    int lane = threadIdx.x;   // 32 threads
    float vals[16];
    for (int i = 0; i < 16; i++) vals[i] = g_logits[b * NP_ + lane * 16 + i];
    int chosen[4];
    for (int r = 0; r < 4; r++) {
        float best = -3.4e38f;
        int bi = 0x7fffffff;
        for (int i = 0; i < 16; i++) {
            int idx = lane * 16 + i;
            bool used = false;
            for (int j = 0; j < r; j++) if (chosen[j] == idx) used = true;
            if (!used && vals[i] > best) { best = vals[i]; bi = idx; }
        }
        for (int off = 16; off; off >>= 1) {
            float ov = __shfl_down_sync(0xffffffffu, best, off);
            int   oi = __shfl_down_sync(0xffffffffu, bi, off);
            if (ov > best || (ov == best && oi < bi)) { best = ov; bi = oi; }
        }
        bi = __shfl_sync(0xffffffffu, bi, 0);
        chosen[r] = bi;
    }
    if (lane == 0) {
        for (int i = 0; i < 3; i++)
            for (int j = i + 1; j < 4; j++)
                if (chosen[j] < chosen[i]) { int t = chosen[i]; chosen[i] = chosen[j]; chosen[j] = t; }
        for (int i = 0; i < 4; i++) g_topk[b * 4 + i] = chosen[i];
    }
}

// ---------------------------------------------------------------------------
// Kernel 3: qkvg projection, 512 threads. Warp owns 4 rows (x-loads become
// warp broadcasts), lane owns 4 cols; f32x2 pairs over n.
// ---------------------------------------------------------------------------
__global__ void qkvg_kernel(const float* __restrict__ x,
                            const float* __restrict__ W) {
    extern __shared__ float sm3[];
    float* xs = sm3;            // 64*128
    float* ws = sm3 + 64 * 128; // 128*128, layout [k][n]
    int b  = blockIdx.y;
    int n0 = blockIdx.x * 128;
    int tid = threadIdx.x;      // 512

    for (int i = tid; i < 2048; i += 512) {
        int m  = i >> 5;
        int c4 = i & 31;
        int tok = g_topk[b * 4 + (m >> 4)] * T0_ + (m & 15);
        reinterpret_cast<float4*>(xs)[i] =
            reinterpret_cast<const float4*>(x + ((size_t)b * T_ + tok) * C_)[c4];
    }
    for (int i = tid; i < 4096; i += 512) {
        int n  = i >> 5;
        int k4 = i & 31;
        float4 wv = reinterpret_cast<const float4*>(W + (size_t)(n0 + n) * C_)[k4];
        int k = k4 * 4;
        ws[(k + 0) * 128 + n] = wv.x;
        ws[(k + 1) * 128 + n] = wv.y;
        ws[(k + 2) * 128 + n] = wv.z;
        ws[(k + 3) * 128 + n] = wv.w;
    }
    __syncthreads();

    int ty = tid >> 5;   // 0..15 -> rows ty*4..ty*4+3 (warp-uniform)
    int tx = tid & 31;   // cols tx*4..tx*4+3
    float2 acc2[4][2];
#pragma unroll
    for (int mm = 0; mm < 4; mm++) {
        acc2[mm][0] = make_float2(0.f, 0.f);
        acc2[mm][1] = make_float2(0.f, 0.f);
    }

#pragma unroll 4
    for (int k = 0; k < 128; k++) {
        float4 bv = reinterpret_cast<const float4*>(ws + k * 128)[tx];
        float2 bp0 = make_float2(bv.x, bv.y);
        float2 bp1 = make_float2(bv.z, bv.w);
#pragma unroll
        for (int mm = 0; mm < 4; mm++) {
            float a = xs[(ty * 4 + mm) * 128 + k];   // warp broadcast
            float2 ap = make_float2(a, a);
            ffma2(acc2[mm][0], ap, bp0);
            ffma2(acc2[mm][1], ap, bp1);
        }
    }
#pragma unroll
    for (int mm = 0; mm < 4; mm++) {
        int m = ty * 4 + mm;
        float4 o = make_float4(acc2[mm][0].x, acc2[mm][0].y, acc2[mm][1].x, acc2[mm][1].y);
        reinterpret_cast<float4*>(g_qkvg + ((size_t)(b * 64 + m)) * 4096 + n0)[tx] = o;
    }
}

// ---------------------------------------------------------------------------
// Kernel 4: attention. 128 blocks x 512 threads (2 per (b,h), parity split).
// ---------------------------------------------------------------------------
__global__ void attn_kernel(const float* __restrict__ cosp,
                            const float* __restrict__ sinp,
                            const float* __restrict__ sink,
                            const float* __restrict__ tao) {
    extern __shared__ float sm4[];
    float* qs  = sm4;                        // 33*132 (own query rows)
    float* ks_ = sm4 + 33 * 132;             // 65*132
    float* vs  = ks_ + 65 * 132;             // 65*132
    float* att = vs + 65 * 132;              // 33*66

    int blk  = blockIdx.x;
    int bh   = blk >> 1;
    int half = blk & 1;
    int b = bh >> 3;
    int h = bh & 7;
    int nrows = 33 - half;                   // 33 or 32
    int tid  = threadIdx.x;                  // 512
    int warp = tid >> 5;                     // 0..15
    int lane = tid & 31;
    float tao0 = tao[0], tao1 = tao[1];

    // zero att (upper triangle must be 0 for guard-free AV)
    for (int i = tid; i < 33 * 66; i += 512) att[i] = 0.f;

    // prep: k,v for all 65 rows; q only for own-parity rows
    for (int s = warp; s < S_; s += 16) {
        const float* qsrc;
        const float* ksrc;
        const float* vsrc;
        if (s == 0) {
            qsrc = sink + h * C_;
            ksrc = qsrc;
            vsrc = qsrc;
        } else {
            int sp = s - 1;
            int j = sp >> 4, r = sp & 15;
            size_t base = (size_t)(b * 64 + j * 16) * 4096 + (size_t)(r & 3) * 1024 + h * C_;
            qsrc = g_qkvg + base + (size_t)((r >> 2) + 0) * 4096;
            ksrc = g_qkvg + base + (size_t)((r >> 2) + 4) * 4096;
            vsrc = g_qkvg + base + (size_t)((r >> 2) + 8) * 4096;
        }
        float c0 = cosp[s * 64 + lane],      s0 = sinp[s * 64 + lane];
        float c1 = cosp[s * 64 + lane + 32], s1 = sinp[s * 64 + lane + 32];

        // k (always)
        {
            float a0 = ksrc[lane], a1 = ksrc[lane + 32], a2 = ksrc[lane + 64], a3 = ksrc[lane + 96];
            float o0 =  a0 * c0 + a2 * s0;
            float o2 = -a0 * s0 + a2 * c0;
            float o1 =  a1 * c1 + a3 * s1;
            float o3 = -a1 * s1 + a3 * c1;
            float ss = o0 * o0 + o1 * o1 + o2 * o2 + o3 * o3;
            for (int off = 16; off; off >>= 1) ss += __shfl_xor_sync(0xffffffffu, ss, off);
            float rn = rsqrtf(ss * (1.0f / 128.0f) + EPS_) * tao1;
            ks_[s * 132 + lane]      = o0 * rn;
            ks_[s * 132 + lane + 32] = o1 * rn;
            ks_[s * 132 + lane + 64] = o2 * rn;
            ks_[s * 132 + lane + 96] = o3 * rn;
        }
        // v (always)
        vs[s * 132 + lane]      = vsrc[lane];
        vs[s * 132 + lane + 32] = vsrc[lane + 32];
        vs[s * 132 + lane + 64] = vsrc[lane + 64];
        vs[s * 132 + lane + 96] = vsrc[lane + 96];
        // q (own parity only)
        if ((s & 1) == half) {
            int i = s >> 1;
            float a0 = qsrc[lane], a1 = qsrc[lane + 32], a2 = qsrc[lane + 64], a3 = qsrc[lane + 96];
            float o0 =  a0 * c0 + a2 * s0;
            float o2 = -a0 * s0 + a2 * c0;
            float o1 =  a1 * c1 + a3 * s1;
            float o3 = -a1 * s1 + a3 * c1;
            float ss = o0 * o0 + o1 * o1 + o2 * o2 + o3 * o3;
            for (int off = 16; off; off >>= 1) ss += __shfl_xor_sync(0xffffffffu, ss, off);
            float rn = rsqrtf(ss * (1.0f / 128.0f) + EPS_) * tao0;
            qs[i * 132 + lane]      = o0 * rn;
            qs[i * 132 + lane + 32] = o1 * rn;
            qs[i * 132 + lane + 64] = o2 * rn;
            qs[i * 132 + lane + 96] = o3 * rn;
        }
    }
    __syncthreads();

    // ---- Score phase: task = (group of 4 own rows, 32-key chunk) -----------
    const float scale = 0.08838834764831845f;  // 1/sqrt(128)
    int ngroups = (nrows + 3) >> 2;
    for (int task = warp; task < ngroups * 3; task += 16) {
        int g = task / 3;
        int c = task - g * 3;
        int i0 = g * 4;
        int imax = min(i0 + 3, nrows - 1);
        int smax = 2 * imax + half;
        int t0 = c * 32;
        if (t0 > smax) continue;
        int t  = t0 + lane;
        int te = (t < 64) ? t : 64;
        int ie0 = min(i0 + 0, nrows - 1);
        int ie1 = min(i0 + 1, nrows - 1);
        int ie2 = min(i0 + 2, nrows - 1);
        int ie3 = min(i0 + 3, nrows - 1);

        const float4* kr = reinterpret_cast<const float4*>(ks_ + te * 132);
        const float4* q0 = reinterpret_cast<const float4*>(qs + ie0 * 132);
        const float4* q1 = reinterpret_cast<const float4*>(qs + ie1 * 132);
        const float4* q2 = reinterpret_cast<const float4*>(qs + ie2 * 132);
        const float4* q3 = reinterpret_cast<const float4*>(qs + ie3 * 132);

        float2 p00 = {0,0}, p01 = {0,0}, p10 = {0,0}, p11 = {0,0};
        float2 p20 = {0,0}, p21 = {0,0}, p30 = {0,0}, p31 = {0,0};
#pragma unroll 8
        for (int c4 = 0; c4 < 32; c4++) {
            float4 kv = kr[c4];
            float2 k0 = make_float2(kv.x, kv.y);
            float2 k1 = make_float2(kv.z, kv.w);
            float4 v0 = q0[c4];
            ffma2(p00, make_float2(v0.x, v0.y), k0);
            ffma2(p01, make_float2(v0.z, v0.w), k1);
            float4 v1 = q1[c4];
            ffma2(p10, make_float2(v1.x, v1.y), k0);
            ffma2(p11, make_float2(v1.z, v1.w), k1);
            float4 v2 = q2[c4];
            ffma2(p20, make_float2(v2.x, v2.y), k0);
            ffma2(p21, make_float2(v2.z, v2.w), k1);
            float4 v3 = q3[c4];
            ffma2(p30, make_float2(v3.x, v3.y), k0);
            ffma2(p31, make_float2(v3.z, v3.w), k1);
        }
        float r0 = (p00.x + p00.y) + (p01.x + p01.y);
        float r1 = (p10.x + p10.y) + (p11.x + p11.y);
        float r2 = (p20.x + p20.y) + (p21.x + p21.y);
        float r3 = (p30.x + p30.y) + (p31.x + p31.y);
        int s0v = 2 * (i0 + 0) + half;
        int s1v = 2 * (i0 + 1) + half;
        int s2v = 2 * (i0 + 2) + half;
        int s3v = 2 * (i0 + 3) + half;
        if (i0 + 0 < nrows && t <= s0v) att[(i0 + 0) * 66 + t] = r0 * scale;
        if (i0 + 1 < nrows && t <= s1v) att[(i0 + 1) * 66 + t] = r1 * scale;
        if (i0 + 2 < nrows && t <= s2v) att[(i0 + 2) * 66 + t] = r2 * scale;
        if (i0 + 3 < nrows && t <= s3v) att[(i0 + 3) * 66 + t] = r3 * scale;
    }
    __syncthreads();

    // ---- Softmax: one warp per own row ------------------------------------
    for (int i = warp; i < nrows; i += 16) {
        int s = 2 * i + half;
        float v0 = (lane      <= s) ? att[i * 66 + lane]      : -3.4e38f;
        float v1 = (lane + 32 <= s) ? att[i * 66 + lane + 32] : -3.4e38f;
        float v2 = (lane + 64 <= s) ? att[i * 66 + lane + 64] : -3.4e38f;
        float m = fmaxf(fmaxf(v0, v1), v2);
        for (int off = 16; off; off >>= 1) m = fmaxf(m, __shfl_xor_sync(0xffffffffu, m, off));
        float e0 = (lane      <= s) ? __expf(v0 - m) : 0.f;
        float e1 = (lane + 32 <= s) ? __expf(v1 - m) : 0.f;
        float e2 = (lane + 64 <= s) ? __expf(v2 - m) : 0.f;
        float sum = e0 + e1 + e2;
        for (int off = 16; off; off >>= 1) sum += __shfl_xor_sync(0xffffffffu, sum, off);
        float inv = 1.f / sum;
        if (lane      <= s) att[i * 66 + lane]      = e0 * inv;
        if (lane + 32 <= s) att[i * 66 + lane + 32] = e1 * inv;
        if (lane + 64 <= s) att[i * 66 + lane + 64] = e2 * inv;
    }
    __syncthreads();

    // ---- AV phase: warp owns rows i = warp + 16*jj ------------------------
    {
        int nj = (warp < nrows) ? ((nrows - warp + 15) >> 4) : 0;   // 0..3
        float2 accp[3][2];
#pragma unroll
        for (int jj = 0; jj < 3; jj++) {
            accp[jj][0] = make_float2(0.f, 0.f);
            accp[jj][1] = make_float2(0.f, 0.f);
        }
        if (nj > 0) {
            int ilast = warp + 16 * (nj - 1);
            int tmax = 2 * ilast + half;
            for (int t = 0; t <= tmax; t++) {
                float4 vv = *reinterpret_cast<const float4*>(vs + t * 132 + lane * 4);
                float2 vp0 = make_float2(vv.x, vv.y);
                float2 vp1 = make_float2(vv.z, vv.w);
#pragma unroll
                for (int jj = 0; jj < 3; jj++) {
                    if (jj < nj) {
                        float a = att[(warp + 16 * jj) * 66 + t];   // 0 for t > s
                        float2 ap = make_float2(a, a);
                        ffma2(accp[jj][0], ap, vp0);
                        ffma2(accp[jj][1], ap, vp1);
                    }
                }
            }
#pragma unroll
            for (int jj = 0; jj < 3; jj++) {
                if (jj < nj) {
                    int i = warp + 16 * jj;
                    int s = 2 * i + half;
                    if (s == 0) continue;
                    int sp = s - 1;
                    int jp = sp >> 4, r = sp & 15;
                    const float* gp = g_qkvg + (size_t)(b * 64 + jp * 16 + 12 + (r >> 2)) * 4096
                                      + (size_t)(r & 3) * 1024 + h * C_ + lane * 4;
                    float4 gv = *reinterpret_cast<const float4*>(gp);
                    float4 o;
                    o.x = accp[jj][0].x / (1.f + __expf(-gv.x));
                    o.y = accp[jj][0].y / (1.f + __expf(-gv.y));
                    o.z = accp[jj][1].x / (1.f + __expf(-gv.z));
                    o.w = accp[jj][1].y / (1.f + __expf(-gv.w));
                    *reinterpret_cast<float4*>(g_y + (size_t)(b * 64 + sp) * 1024 + h * C_ + lane * 4) = o;
                }
            }
        }
    }
}

// ---------------------------------------------------------------------------
// Kernel 5: output GEMM (split-K), f32x2 pairs over n.
// ---------------------------------------------------------------------------
__global__ void outgemm_kernel(const float* __restrict__ Wout) {
    __shared__ float ys[64 * 128];
    __shared__ float ws[128 * 32];   // [k][n]
    int n0  = blockIdx.x * 32;
    int ksb = blockIdx.y;
    int b   = blockIdx.z;
    int tid = threadIdx.x;           // 256

    float2 acc2[2][2];
#pragma unroll
    for (int mm = 0; mm < 2; mm++) {
        acc2[mm][0] = make_float2(0.f, 0.f);
        acc2[mm][1] = make_float2(0.f, 0.f);
    }

    for (int kc = 0; kc < 2; kc++) {
        int k0 = ksb * 256 + kc * 128;
        __syncthreads();
        for (int i = tid; i < 2048; i += 256) {
            int m = i >> 5, k4 = i & 31;
            reinterpret_cast<float4*>(ys)[i] =
                *reinterpret_cast<const float4*>(g_y + (size_t)(b * 64 + m) * 1024 + k0 + k4 * 4);
        }
        for (int i = tid; i < 1024; i += 256) {
            int n = i >> 5, k4 = i & 31;
            float4 w4 = *reinterpret_cast<const float4*>(Wout + (size_t)(n0 + n) * 1024 + k0 + k4 * 4);
            int k = k4 * 4;
            ws[(k + 0) * 32 + n] = w4.x;
            ws[(k + 1) * 32 + n] = w4.y;
            ws[(k + 2) * 32 + n] = w4.z;
            ws[(k + 3) * 32 + n] = w4.w;
        }
        __syncthreads();

        int ty = tid >> 3;   // rows {ty, ty+32}
        int tx = tid & 7;    // cols tx*4..+3
#pragma unroll 4
        for (int k = 0; k < 128; k++) {
            float4 b4 = reinterpret_cast<const float4*>(ws + k * 32)[tx];
            float2 bp0 = make_float2(b4.x, b4.y);
            float2 bp1 = make_float2(b4.z, b4.w);
            float a0 = ys[ty * 128 + k];
            float a1 = ys[(ty + 32) * 128 + k];
            float2 ap0 = make_float2(a0, a0);
            float2 ap1 = make_float2(a1, a1);
            ffma2(acc2[0][0], ap0, bp0);
            ffma2(acc2[0][1], ap0, bp1);
            ffma2(acc2[1][0], ap1, bp0);
            ffma2(acc2[1][1], ap1, bp1);
        }
    }

    int ty = tid >> 3, tx = tid & 7;
#pragma unroll
    for (int mm = 0; mm < 2; mm++) {
        int m = ty + mm * 32;
        float4 o = make_float4(acc2[mm][0].x, acc2[mm][0].y, acc2[mm][1].x, acc2[mm][1].y);
        reinterpret_cast<float4*>(g_part + (size_t)ksb * 65536
                                  + (size_t)(b * 64 + m) * 128 + n0)[tx] = o;
    }
}

__global__ void reduce_kernel(float* __restrict__ out) {
    int i = blockIdx.x * 256 + threadIdx.x;
    out[i] = ((g_part[i] + g_part[65536 + i]) + g_part[131072 + i]) + g_part[196608 + i];
}

// ---------------------------------------------------------------------------
extern "C" void kernel_launch(void* const* d_in, const int* in_sizes, int n_in,
                              void* d_out, int out_size) {
    const float* x      = (const float*)d_in[0];
    const float* cosp   = (const float*)d_in[1];
    const float* sinp   = (const float*)d_in[2];
    const float* sink   = (const float*)d_in[3];
    const float* W_qkvg = (const float*)d_in[4];
    const float* patchw = (const float*)d_in[5];
    const float* W_out  = (const float*)d_in[6];
    const float* tao    = (const float*)d_in[7];
    float* out = (float*)d_out;

    const int smem3 = (64 * 128 + 128 * 128) * 4;                       // 96 KB
    const int smem4 = (33 * 132 + 2 * 65 * 132 + 33 * 66) * 4;          // ~93 KB
    cudaFuncSetAttribute(qkvg_kernel, cudaFuncAttributeMaxDynamicSharedMemorySize, smem3);
    cudaFuncSetAttribute(attn_kernel, cudaFuncAttributeMaxDynamicSharedMemorySize, smem4);

    patch_score_kernel<<<B_ * NP_, 256>>>(x, patchw);
    topk_kernel<<<B_, 32>>>();
    qkvg_kernel<<<dim3(32, B_), 512, smem3>>>(x, W_qkvg);
    attn_kernel<<<B_ * H_ * 2, 512, smem4>>>(cosp, sinp, sink, tao);
    outgemm_kernel<<<dim3(4, 4, B_), 256>>>(W_out);
    reduce_kernel<<<B_ * 64 * 128 / 256, 256>>>(out);
}